// round 8
// baseline (speedup 1.0000x reference)
#include <cuda_runtime.h>
#include <math.h>

#define S_LEN 8192
#define DHALF 64
#define D2    128
#define BM    64
#define BN    64
#define QPITCH 132   // 128 + 4 pad (rows 16B-aligned: 132*4=528=33*16)
#define PPITCH 68    // 64 + 4 pad
#define NTHREADS 256

#define PHI_F       1.61803398874989484820f
#define INV_2PI_F   0.15915494309189535f
#define ANG_STEP_F  0.00153398078788564122f  // 2*pi/4096
#define INV_SQRT128 0.08838834764831845f
#define BIG_NEG     (-1e30f)

// packed f32x2 helpers (Blackwell FFMA2 path is PTX-only)
#define FMA2(d, a, b) \
    asm("fma.rn.f32x2 %0, %1, %2, %0;" : "+l"(d) : "l"(a), "l"(b))
#define MUL2(d, a, b) \
    asm("mul.rn.f32x2 %0, %1, %2;" : "=l"(d) : "l"(a), "l"(b))
#define PACK2(d, lo, hi) \
    asm("mov.b64 %0, {%1, %2};" : "=l"(d) : "f"(lo), "f"(hi))
#define UNPACK2(lo, hi, s) \
    asm("mov.b64 {%0, %1}, %2;" : "=f"(lo), "=f"(hi) : "l"(s))

// scratch for `retrieved` (B,S,128)
__device__ float g_R[2 * S_LEN * D2];

__global__ __launch_bounds__(NTHREADS, 1)
void attn_kernel(const float* __restrict__ sr, const float* __restrict__ si,
                 const float* __restrict__ pos, const float* __restrict__ wq,
                 const float* __restrict__ bq)
{
    extern __shared__ float sm[];
    float* Qs = sm;                          // BM * QPITCH
    float* Ks = sm + BM * QPITCH;            // BN * QPITCH
    float* Ps = sm + (BM + BN) * QPITCH;     // BM * PPITCH

    const int b    = blockIdx.y;
    const int pair = blockIdx.x;             // 0..63
    const int tid  = threadIdx.x;
    const int tx   = tid & 15;
    const int ty   = tid >> 4;

    for (int which = 0; which < 2; which++) {
        const int qt = which ? (127 - pair) : pair;
        const int q0 = qt * BM;

        // ---- Q prologue: theta -> LUT-quantized cos ----
        for (int u = tid; u < BM * D2; u += NTHREADS) {
            const int row = u >> 7;
            const int col = u & 127;
            const int s   = q0 + row;
            const int d   = (col < DHALF) ? col : col - DHALF;
            const float x = (col < DHALF) ? sr[((size_t)b * S_LEN + s) * DHALF + d]
                                          : si[((size_t)b * S_LEN + s) * DHALF + d];
            const float wl = 1.0f + fabsf(wq[d]);
            float th = x / wl + bq[d] + pos[s] * PHI_F;
            float fr = th * INV_2PI_F;
            fr = fr - floorf(fr);
            int idx = (int)floorf(fr * 4096.0f);
            idx = min(max(idx, 0), 4095);
            Qs[row * QPITCH + col] = cosf((float)idx * ANG_STEP_F);
        }
        __syncthreads();

        // o2[i][j2] packs output columns (2*tx + 32*j2, 2*tx + 32*j2 + 1)
        float m_i[4], l_i[4];
        unsigned long long o2[4][4];
        #pragma unroll
        for (int i = 0; i < 4; i++) {
            m_i[i] = BIG_NEG; l_i[i] = 0.0f;
            #pragma unroll
            for (int j = 0; j < 4; j++) o2[i][j] = 0ULL;
        }

        for (int kt = 0; kt <= qt; kt++) {
            // ---- load K tile (64 x 128) as float4 ----
            for (int u = tid; u < BN * 32; u += NTHREADS) {
                const int row = u >> 5;
                const int c4  = u & 31;
                const int s   = kt * BN + row;
                const float* src = (c4 < 16)
                    ? sr + ((size_t)b * S_LEN + s) * DHALF + c4 * 4
                    : si + ((size_t)b * S_LEN + s) * DHALF + (c4 - 16) * 4;
                *(float4*)&Ks[row * QPITCH + c4 * 4] = *(const float4*)src;
            }
            __syncthreads();

            // ---- GEMM1: scores = Q @ K^T (packed f32x2, lanes = even/odd k) ----
            unsigned long long acc2[4][4];
            #pragma unroll
            for (int i = 0; i < 4; i++)
                #pragma unroll
                for (int j = 0; j < 4; j++) acc2[i][j] = 0ULL;

            #pragma unroll 4
            for (int kk = 0; kk < D2; kk += 4) {
                ulonglong2 qv[4], kv[4];
                #pragma unroll
                for (int i = 0; i < 4; i++)
                    qv[i] = *(const ulonglong2*)(Qs + (ty + 16 * i) * QPITCH + kk);
                #pragma unroll
                for (int j = 0; j < 4; j++)
                    kv[j] = *(const ulonglong2*)(Ks + (tx + 16 * j) * QPITCH + kk);
                #pragma unroll
                for (int i = 0; i < 4; i++)
                    #pragma unroll
                    for (int j = 0; j < 4; j++) {
                        FMA2(acc2[i][j], qv[i].x, kv[j].x);
                        FMA2(acc2[i][j], qv[i].y, kv[j].y);
                    }
            }

            const bool diag   = (kt == qt);
            const bool tile00 = (qt == 0); // kt==0 too

            // ---- scale / mask / online softmax ----
            #pragma unroll
            for (int i = 0; i < 4; i++) {
                const int qg = q0 + ty + 16 * i;
                float sc[4];
                #pragma unroll
                for (int j = 0; j < 4; j++) {
                    float lo, hi;
                    UNPACK2(lo, hi, acc2[i][j]);
                    const int kg = kt * BN + tx + 16 * j;
                    float v = (lo + hi) * INV_SQRT128;
                    if (diag && kg > qg) v = BIG_NEG;
                    if (tile00 && qg == 0 && kg == 0) v = 0.0f;
                    sc[j] = v;
                }
                float mt = fmaxf(fmaxf(sc[0], sc[1]), fmaxf(sc[2], sc[3]));
                #pragma unroll
                for (int off = 8; off >= 1; off >>= 1)
                    mt = fmaxf(mt, __shfl_xor_sync(0xffffffffu, mt, off, 16));
                const float mn   = fmaxf(m_i[i], mt);
                const float corr = __expf(m_i[i] - mn);
                float rs = 0.0f;
                #pragma unroll
                for (int j = 0; j < 4; j++) {
                    const float p = __expf(sc[j] - mn);
                    Ps[(ty + 16 * i) * PPITCH + tx + 16 * j] = p;
                    rs += p;
                }
                #pragma unroll
                for (int off = 8; off >= 1; off >>= 1)
                    rs += __shfl_xor_sync(0xffffffffu, rs, off, 16);
                l_i[i] = l_i[i] * corr + rs;
                m_i[i] = mn;
                unsigned long long c2;
                PACK2(c2, corr, corr);
                #pragma unroll
                for (int j = 0; j < 4; j++)
                    MUL2(o2[i][j], o2[i][j], c2);
            }
            __syncthreads();   // Ps visible

            // ---- GEMM2: O += P @ K (packed; thread owns adjacent col pairs) ----
            #pragma unroll 4
            for (int kk = 0; kk < BN; kk += 4) {
                float pr[4][4];
                #pragma unroll
                for (int i = 0; i < 4; i++) {
                    float4 t = *(const float4*)(Ps + (ty + 16 * i) * PPITCH + kk);
                    pr[i][0] = t.x; pr[i][1] = t.y; pr[i][2] = t.z; pr[i][3] = t.w;
                }
                #pragma unroll
                for (int t = 0; t < 4; t++) {
                    unsigned long long kv2[4];
                    #pragma unroll
                    for (int j = 0; j < 4; j++)
                        kv2[j] = *(const unsigned long long*)
                                 (Ks + (kk + t) * QPITCH + 2 * tx + 32 * j);
                    unsigned long long p2[4];
                    #pragma unroll
                    for (int i = 0; i < 4; i++)
                        PACK2(p2[i], pr[i][t], pr[i][t]);
                    #pragma unroll
                    for (int i = 0; i < 4; i++)
                        #pragma unroll
                        for (int j = 0; j < 4; j++)
                            FMA2(o2[i][j], p2[i], kv2[j]);
                }
            }
            __syncthreads();   // before K tile overwrite
        }

        // ---- epilogue: normalize + store retrieved ----
        #pragma unroll
        for (int i = 0; i < 4; i++) {
            const float inv = 1.0f / l_i[i];
            const int row = q0 + ty + 16 * i;
            float* dst = g_R + ((size_t)b * S_LEN + row) * D2;
            #pragma unroll
            for (int j = 0; j < 4; j++) {
                float lo, hi;
                UNPACK2(lo, hi, o2[i][j]);
                dst[2 * tx + 32 * j]     = lo * inv;
                dst[2 * tx + 32 * j + 1] = hi * inv;
            }
        }
        __syncthreads();   // before Qs reuse
    }
}

// EMA scan: linear recurrence; (1-a)^64 ~ 2e-21 so a 64-step lookback seed is
// exact to fp32. out[b,s,d] = ema(r[d] + r[d+64]) by linearity.
__global__ void ema_kernel(const float* __restrict__ alpha, float* __restrict__ out)
{
    const int b     = blockIdx.y;
    const int chunk = blockIdx.x;  // 64 s-positions each
    const int d     = threadIdx.x; // 0..63

    const float a = 1.0f / (1.0f + expf(-alpha[0]));
    const float w = 1.0f - a;

    const int s0     = chunk * 64;
    const int sstart = (s0 >= 64) ? (s0 - 64) : 0;
    const float* base = g_R + (size_t)b * S_LEN * D2;

    float ema = 0.0f;
    #pragma unroll 4
    for (int s = sstart; s < s0 + 64; s++) {
        const float rc = base[s * D2 + d] + base[s * D2 + d + DHALF];
        ema = fmaf(a, rc, w * ema);
        if (s >= s0)
            out[((size_t)b * S_LEN + s) * DHALF + d] = ema;
    }
}

extern "C" void kernel_launch(void* const* d_in, const int* in_sizes, int n_in,
                              void* d_out, int out_size)
{
    const float* sr    = (const float*)d_in[0];
    const float* si    = (const float*)d_in[1];
    const float* pos   = (const float*)d_in[2];
    const float* wq    = (const float*)d_in[3];
    const float* bq    = (const float*)d_in[4];
    const float* alpha = (const float*)d_in[5];
    float* out = (float*)d_out;

    const int smem = (BM * QPITCH + BN * QPITCH + BM * PPITCH) * (int)sizeof(float);
    cudaFuncSetAttribute(attn_kernel, cudaFuncAttributeMaxDynamicSharedMemorySize, smem);

    attn_kernel<<<dim3(64, 2), NTHREADS, smem>>>(sr, si, pos, wq, bq);
    ema_kernel<<<dim3(S_LEN / 64, 2), DHALF>>>(alpha, out);
}

// round 10
// speedup vs baseline: 1.0392x; 1.0392x over previous
#include <cuda_runtime.h>
#include <math.h>

#define S_LEN 8192
#define DHALF 64
#define D2    128
#define BM    64
#define BN    64
#define QPITCH 132   // 128 + 4 pad (rows 16B-aligned: 132*4=528=33*16)
#define PPITCH 68    // 64 + 4 pad
#define NTHREADS 256

#define PHI_F       1.61803398874989484820f
#define INV_2PI_F   0.15915494309189535f
#define ANG_STEP_F  0.00153398078788564122f  // 2*pi/4096
#define INV_SQRT128 0.08838834764831845f
#define BIG_NEG     (-1e30f)

// packed f32x2 helpers (Blackwell FFMA2 path is PTX-only)
#define FMA2(d, a, b) \
    asm("fma.rn.f32x2 %0, %1, %2, %0;" : "+l"(d) : "l"(a), "l"(b))
#define MUL2(d, a, b) \
    asm("mul.rn.f32x2 %0, %1, %2;" : "=l"(d) : "l"(a), "l"(b))
#define PACK2(d, lo, hi) \
    asm("mov.b64 %0, {%1, %2};" : "=l"(d) : "f"(lo), "f"(hi))
#define UNPACK2(lo, hi, s) \
    asm("mov.b64 {%0, %1}, %2;" : "=f"(lo), "=f"(hi) : "l"(s))

// scratch for `retrieved` (B,S,128)
__device__ float g_R[2 * S_LEN * D2];

__global__ __launch_bounds__(NTHREADS, 1)
void attn_kernel(const float* __restrict__ sr, const float* __restrict__ si,
                 const float* __restrict__ pos, const float* __restrict__ wq,
                 const float* __restrict__ bq)
{
    extern __shared__ float sm[];
    float* Qs  = sm;                              // BM * QPITCH
    float* Ks0 = sm + BM * QPITCH;                // BN * QPITCH (double buffer 0)
    float* Ks1 = sm + (BM + BN) * QPITCH;         // BN * QPITCH (double buffer 1)
    float* Ps  = sm + (BM + 2 * BN) * QPITCH;     // BM * PPITCH

    const int b    = blockIdx.y;
    const int pair = blockIdx.x;             // 0..63
    const int tid  = threadIdx.x;
    const int tx   = tid & 15;
    const int ty   = tid >> 4;

    // this thread's fixed K-load slots: u = tid + 256*k8, row = u>>5, c4 = u&31
    const int krow0 = tid >> 5;              // rows krow0 + 8*k8
    const int kc4   = tid & 31;

    for (int which = 0; which < 2; which++) {
        const int qt = which ? (127 - pair) : pair;
        const int q0 = qt * BM;

        // ---- Q prologue: theta -> LUT-quantized cos ----
        for (int u = tid; u < BM * D2; u += NTHREADS) {
            const int row = u >> 7;
            const int col = u & 127;
            const int s   = q0 + row;
            const int d   = (col < DHALF) ? col : col - DHALF;
            const float x = (col < DHALF) ? sr[((size_t)b * S_LEN + s) * DHALF + d]
                                          : si[((size_t)b * S_LEN + s) * DHALF + d];
            const float wl = 1.0f + fabsf(wq[d]);
            float th = x / wl + bq[d] + pos[s] * PHI_F;
            float fr = th * INV_2PI_F;
            fr = fr - floorf(fr);
            int idx = (int)floorf(fr * 4096.0f);
            idx = min(max(idx, 0), 4095);
            Qs[row * QPITCH + col] = cosf((float)idx * ANG_STEP_F);
        }

        // ---- K tile 0 -> buffer 0 ----
        #pragma unroll
        for (int k8 = 0; k8 < 8; k8++) {
            const int row = krow0 + 8 * k8;
            const int s   = row;             // kt = 0
            const float* src = (kc4 < 16)
                ? sr + ((size_t)b * S_LEN + s) * DHALF + kc4 * 4
                : si + ((size_t)b * S_LEN + s) * DHALF + (kc4 - 16) * 4;
            *(float4*)&Ks0[row * QPITCH + kc4 * 4] = *(const float4*)src;
        }
        __syncthreads();

        // o2[i][j2] packs output columns (2*tx + 32*j2, 2*tx + 32*j2 + 1)
        float m_i[4], l_i[4];
        unsigned long long o2[4][4];
        #pragma unroll
        for (int i = 0; i < 4; i++) {
            m_i[i] = BIG_NEG; l_i[i] = 0.0f;
            #pragma unroll
            for (int j = 0; j < 4; j++) o2[i][j] = 0ULL;
        }

        for (int kt = 0; kt <= qt; kt++) {
            float* Ks  = (kt & 1) ? Ks1 : Ks0;
            float* Ksn = (kt & 1) ? Ks0 : Ks1;

            // ---- prefetch next K tile into regs (hidden behind GEMM1) ----
            const int nkt = (kt < qt) ? kt + 1 : qt;  // clamped; redundant on last
            float4 kreg[8];
            #pragma unroll
            for (int k8 = 0; k8 < 8; k8++) {
                const int row = krow0 + 8 * k8;
                const int s   = nkt * BN + row;
                const float* src = (kc4 < 16)
                    ? sr + ((size_t)b * S_LEN + s) * DHALF + kc4 * 4
                    : si + ((size_t)b * S_LEN + s) * DHALF + (kc4 - 16) * 4;
                kreg[k8] = *(const float4*)src;
            }

            // ---- GEMM1: scores = Q @ K^T (packed f32x2, lanes = even/odd k) ----
            unsigned long long acc2[4][4];
            #pragma unroll
            for (int i = 0; i < 4; i++)
                #pragma unroll
                for (int j = 0; j < 4; j++) acc2[i][j] = 0ULL;

            #pragma unroll 4
            for (int kk = 0; kk < D2; kk += 4) {
                ulonglong2 qv[4], kv[4];
                #pragma unroll
                for (int i = 0; i < 4; i++)
                    qv[i] = *(const ulonglong2*)(Qs + (ty + 16 * i) * QPITCH + kk);
                #pragma unroll
                for (int j = 0; j < 4; j++)
                    kv[j] = *(const ulonglong2*)(Ks + (tx + 16 * j) * QPITCH + kk);
                #pragma unroll
                for (int i = 0; i < 4; i++)
                    #pragma unroll
                    for (int j = 0; j < 4; j++) {
                        FMA2(acc2[i][j], qv[i].x, kv[j].x);
                        FMA2(acc2[i][j], qv[i].y, kv[j].y);
                    }
            }

            // ---- store prefetched tile to the other buffer ----
            // (safe: last readers of Ksn were GEMM2 of iter kt-1, before the
            //  end-of-iteration sync; next readers are iter kt+1 after this
            //  iteration's final sync)
            if (kt < qt) {
                #pragma unroll
                for (int k8 = 0; k8 < 8; k8++)
                    *(float4*)&Ksn[(krow0 + 8 * k8) * QPITCH + kc4 * 4] = kreg[k8];
            }

            const bool diag   = (kt == qt);
            const bool tile00 = (qt == 0); // kt==0 too

            // ---- scale / mask / online softmax ----
            #pragma unroll
            for (int i = 0; i < 4; i++) {
                const int qg = q0 + ty + 16 * i;
                float sc[4];
                #pragma unroll
                for (int j = 0; j < 4; j++) {
                    float lo, hi;
                    UNPACK2(lo, hi, acc2[i][j]);
                    const int kg = kt * BN + tx + 16 * j;
                    float v = (lo + hi) * INV_SQRT128;
                    if (diag && kg > qg) v = BIG_NEG;
                    if (tile00 && qg == 0 && kg == 0) v = 0.0f;
                    sc[j] = v;
                }
                float mt = fmaxf(fmaxf(sc[0], sc[1]), fmaxf(sc[2], sc[3]));
                #pragma unroll
                for (int off = 8; off >= 1; off >>= 1)
                    mt = fmaxf(mt, __shfl_xor_sync(0xffffffffu, mt, off, 16));
                const float mn   = fmaxf(m_i[i], mt);
                const float corr = __expf(m_i[i] - mn);
                float rs = 0.0f;
                #pragma unroll
                for (int j = 0; j < 4; j++) {
                    const float p = __expf(sc[j] - mn);
                    Ps[(ty + 16 * i) * PPITCH + tx + 16 * j] = p;
                    rs += p;
                }
                #pragma unroll
                for (int off = 8; off >= 1; off >>= 1)
                    rs += __shfl_xor_sync(0xffffffffu, rs, off, 16);
                l_i[i] = l_i[i] * corr + rs;
                m_i[i] = mn;
                unsigned long long c2;
                PACK2(c2, corr, corr);
                #pragma unroll
                for (int j = 0; j < 4; j++)
                    MUL2(o2[i][j], o2[i][j], c2);
            }
            __syncthreads();   // Ps visible

            // ---- GEMM2: O += P @ K (packed; thread owns adjacent col pairs) ----
            #pragma unroll 4
            for (int kk = 0; kk < BN; kk += 4) {
                float pr[4][4];
                #pragma unroll
                for (int i = 0; i < 4; i++) {
                    float4 t = *(const float4*)(Ps + (ty + 16 * i) * PPITCH + kk);
                    pr[i][0] = t.x; pr[i][1] = t.y; pr[i][2] = t.z; pr[i][3] = t.w;
                }
                #pragma unroll
                for (int t = 0; t < 4; t++) {
                    unsigned long long kv2[4];
                    #pragma unroll
                    for (int j = 0; j < 4; j++)
                        kv2[j] = *(const unsigned long long*)
                                 (Ks + (kk + t) * QPITCH + 2 * tx + 32 * j);
                    unsigned long long p2[4];
                    #pragma unroll
                    for (int i = 0; i < 4; i++)
                        PACK2(p2[i], pr[i][t], pr[i][t]);
                    #pragma unroll
                    for (int i = 0; i < 4; i++)
                        #pragma unroll
                        for (int j = 0; j < 4; j++)
                            FMA2(o2[i][j], p2[i], kv2[j]);
                }
            }
            __syncthreads();   // Ps consumed + next-K STS visible
        }

        // ---- epilogue: normalize + store retrieved ----
        #pragma unroll
        for (int i = 0; i < 4; i++) {
            const float inv = 1.0f / l_i[i];
            const int row = q0 + ty + 16 * i;
            float* dst = g_R + ((size_t)b * S_LEN + row) * D2;
            #pragma unroll
            for (int j = 0; j < 4; j++) {
                float lo, hi;
                UNPACK2(lo, hi, o2[i][j]);
                dst[2 * tx + 32 * j]     = lo * inv;
                dst[2 * tx + 32 * j + 1] = hi * inv;
            }
        }
        __syncthreads();   // before Qs / K-buffer reuse
    }
}

// EMA scan: linear recurrence; (1-a)^64 ~ 2e-21 so a 64-step lookback seed is
// exact to fp32. Chunk=32 doubles block count vs 64 (occupancy was 5%).
#define EMA_CHUNK 32
__global__ void ema_kernel(const float* __restrict__ alpha, float* __restrict__ out)
{
    const int b     = blockIdx.y;
    const int chunk = blockIdx.x;
    const int d     = threadIdx.x; // 0..63

    const float a = 1.0f / (1.0f + expf(-alpha[0]));
    const float w = 1.0f - a;

    const int s0     = chunk * EMA_CHUNK;
    const int sstart = (s0 >= 64) ? (s0 - 64) : 0;
    const float* base = g_R + (size_t)b * S_LEN * D2;

    float ema = 0.0f;
    #pragma unroll 4
    for (int s = sstart; s < s0 + EMA_CHUNK; s++) {
        const float rc = base[s * D2 + d] + base[s * D2 + d + DHALF];
        ema = fmaf(a, rc, w * ema);
        if (s >= s0)
            out[((size_t)b * S_LEN + s) * DHALF + d] = ema;
    }
}

extern "C" void kernel_launch(void* const* d_in, const int* in_sizes, int n_in,
                              void* d_out, int out_size)
{
    const float* sr    = (const float*)d_in[0];
    const float* si    = (const float*)d_in[1];
    const float* pos   = (const float*)d_in[2];
    const float* wq    = (const float*)d_in[3];
    const float* bq    = (const float*)d_in[4];
    const float* alpha = (const float*)d_in[5];
    float* out = (float*)d_out;

    const int smem = ((BM + 2 * BN) * QPITCH + BM * PPITCH) * (int)sizeof(float);
    cudaFuncSetAttribute(attn_kernel, cudaFuncAttributeMaxDynamicSharedMemorySize, smem);

    attn_kernel<<<dim3(64, 2), NTHREADS, smem>>>(sr, si, pos, wq, bq);
    ema_kernel<<<dim3(S_LEN / EMA_CHUNK, 2), DHALF>>>(alpha, out);
}